// round 9
// baseline (speedup 1.0000x reference)
#include <cuda_runtime.h>
#include <cuda_bf16.h>
#include <math.h>
#include <stdint.h>

// Problem constants
#define NB 2
#define NS 2048
#define NTOK (NB * NS)          // 4096
#define DD 1024
#define FF 2048
#define NE 16

// GEMM tiling
#define BM 128
#define BN 128
#define BK 32
#define NTHREADS_G 256          // 8 warps (4 M x 2 N), 32x64 warp tiles
#define MAX_TILES 64            // >= NTOK/BM + NE = 48

// SMEM stage layout (padded, bank-conflict-free for ldmatrix)
#define A_STRIDE 80             // 32 bf16 = 64B data + 16B pad
#define B_STRIDE 272            // 128 bf16 = 256B data + 16B pad
#define OA_H 0
#define OA_L (OA_H + BM * A_STRIDE)            // 10240
#define OB_H (OA_L + BM * A_STRIDE)            // 20480
#define OB_L (OB_H + BK * B_STRIDE)            // 29184
#define STAGE_BYTES (OB_L + BK * B_STRIDE)     // 37888
#define SMEM_GEMM (2 * STAGE_BYTES)            // 75776

// Router
#define RT_WARPS 16
#define SMEM_RT (DD * 17 * 4)   // 69632

// ---------------- device scratch (static globals: allocation-free) ----------
__device__ __nv_bfloat16 g_xh[NTOK * DD];      // gathered tokens hi (8 MB)
__device__ __nv_bfloat16 g_xl[NTOK * DD];      // lo
__device__ __nv_bfloat16 g_hh[NTOK * FF];      // hidden hi (16 MB)
__device__ __nv_bfloat16 g_hl[NTOK * FF];      // lo
__device__ int   g_assign[NTOK];
__device__ float g_wgt[NTOK];
__device__ int   g_perm[NTOK];
__device__ int   g_counts[NE];
__device__ int   g_cursor[NE];
__device__ int   g_row_start[NE];
__device__ int   g_tile_e[MAX_TILES];
__device__ int   g_tile_row[MAX_TILES];
__device__ int   g_tile_rows[MAX_TILES];
__device__ int   g_num_tiles;

// ---------------- helpers ----------------------------------------------------
__device__ __forceinline__ uint32_t smem_u32(const void* p) {
    uint32_t a;
    asm("{ .reg .u64 t; cvta.to.shared.u64 t, %1; cvt.u32.u64 %0, t; }" : "=r"(a) : "l"(p));
    return a;
}
__device__ __forceinline__ void cp16(uint32_t dst, const void* src, uint32_t sz) {
    asm volatile("cp.async.cg.shared.global [%0], [%1], 16, %2;"
                 :: "r"(dst), "l"(src), "r"(sz) : "memory");
}
__device__ __forceinline__ void cp_commit() {
    asm volatile("cp.async.commit_group;" ::: "memory");
}
__device__ __forceinline__ void ldsm_x4(uint32_t* r, uint32_t addr) {
    asm volatile("ldmatrix.sync.aligned.m8n8.x4.shared.b16 {%0,%1,%2,%3}, [%4];"
                 : "=r"(r[0]), "=r"(r[1]), "=r"(r[2]), "=r"(r[3]) : "r"(addr));
}
__device__ __forceinline__ void ldsm_x4_t(uint32_t* r, uint32_t addr) {
    asm volatile("ldmatrix.sync.aligned.m8n8.x4.trans.shared.b16 {%0,%1,%2,%3}, [%4];"
                 : "=r"(r[0]), "=r"(r[1]), "=r"(r[2]), "=r"(r[3]) : "r"(addr));
}
__device__ __forceinline__ void mma_bf16(float* d, const uint32_t* a, const uint32_t* b) {
    asm volatile("mma.sync.aligned.m16n8k16.row.col.f32.bf16.bf16.f32 "
                 "{%0,%1,%2,%3}, {%4,%5,%6,%7}, {%8,%9}, {%0,%1,%2,%3};"
                 : "+f"(d[0]), "+f"(d[1]), "+f"(d[2]), "+f"(d[3])
                 : "r"(a[0]), "r"(a[1]), "r"(a[2]), "r"(a[3]), "r"(b[0]), "r"(b[1]));
}
__device__ __forceinline__ uint32_t pack_bf2(float a, float b) {
    __nv_bfloat162 t = __floats2bfloat162_rn(a, b);
    return *reinterpret_cast<uint32_t*>(&t);
}
__device__ __forceinline__ void sts64(uint32_t addr, uint32_t x, uint32_t y) {
    asm volatile("st.shared.v2.b32 [%0], {%1, %2};" :: "r"(addr), "r"(x), "r"(y) : "memory");
}
__device__ __forceinline__ float gelu_erf(float x) {
    return 0.5f * x * (1.0f + erff(x * 0.70710678118654752440f));
}
// split float4 -> hi uint2 / lo uint2
__device__ __forceinline__ void split4(float4 v, uint2& hi, uint2& lo) {
    float hx = __bfloat162float(__float2bfloat16_rn(v.x));
    float hy = __bfloat162float(__float2bfloat16_rn(v.y));
    float hz = __bfloat162float(__float2bfloat16_rn(v.z));
    float hw = __bfloat162float(__float2bfloat16_rn(v.w));
    hi = make_uint2(pack_bf2(hx, hy), pack_bf2(hz, hw));
    lo = make_uint2(pack_bf2(v.x - hx, v.y - hy), pack_bf2(v.z - hz, v.w - hw));
}

// ---------------- routing ----------------------------------------------------
__global__ void zero_kernel() {
    int t = threadIdx.x;
    if (t < NE) { g_counts[t] = 0; g_cursor[t] = 0; }
}

// router: rw cached in smem (stride 17 -> conflict-free), 16 tokens/block
__global__ __launch_bounds__(512) void router_kernel(
    const float* __restrict__ h, const float* __restrict__ rw)
{
    extern __shared__ float srw[];   // [DD][17]
    int tid = threadIdx.x, lane = tid & 31, wid = tid >> 5;
    for (int i = tid; i < DD * NE; i += 512)
        srw[(i >> 4) * 17 + (i & 15)] = rw[i];
    __syncthreads();

    int tok = blockIdx.x * RT_WARPS + wid;
    const float* x = h + (size_t)tok * DD;
    float acc[NE];
#pragma unroll
    for (int e = 0; e < NE; e++) acc[e] = 0.0f;
    for (int d = lane; d < DD; d += 32) {
        float xv = x[d];
        const float* r = &srw[d * 17];
#pragma unroll
        for (int e = 0; e < NE; e++) acc[e] += xv * r[e];
    }
#pragma unroll
    for (int e = 0; e < NE; e++)
#pragma unroll
        for (int o = 16; o > 0; o >>= 1)
            acc[e] += __shfl_down_sync(0xFFFFFFFFu, acc[e], o);
    if (lane == 0) {
        int best = 0; float bv = acc[0];
#pragma unroll
        for (int e = 1; e < NE; e++)
            if (acc[e] > bv) { bv = acc[e]; best = e; }
        g_assign[tok] = best;
        g_wgt[tok]    = 1.0f / (1.0f + expf(-bv));
        atomicAdd(&g_counts[best], 1);
    }
}

__global__ void plan_kernel() {
    if (threadIdx.x != 0) return;
    int off = 0, t = 0;
    for (int e = 0; e < NE; e++) {
        g_row_start[e] = off;
        int c = g_counts[e];
        for (int r = 0; r < c; r += BM) {
            g_tile_e[t] = e; g_tile_row[t] = off + r;
            g_tile_rows[t] = min(BM, c - r); t++;
        }
        off += c;
    }
    g_num_tiles = t;
}

// merged scatter+gather: block per token; computes sorted position, writes perm
// and the bf16 hi/lo planes of the token row.
__global__ __launch_bounds__(256) void scatter_gather_kernel(const float* __restrict__ h) {
    __shared__ int spos;
    int tok = blockIdx.x;
    if (threadIdx.x == 0) {
        int e = g_assign[tok];
        int p = g_row_start[e] + atomicAdd(&g_cursor[e], 1);
        g_perm[p] = tok;
        spos = p;
    }
    __syncthreads();
    int pos = spos;
    const float4* src = (const float4*)(h + (size_t)tok * DD);
    uint2* dh = (uint2*)(g_xh + (size_t)pos * DD);
    uint2* dl = (uint2*)(g_xl + (size_t)pos * DD);
    float4 v = src[threadIdx.x];
    uint2 hi, lo;
    split4(v, hi, lo);
    dh[threadIdx.x] = hi;
    dl[threadIdx.x] = lo;
}

// ---------------- split-bf16 mma.sync grouped GEMM ---------------------------
// 8 warps (4x2), 32x64 warp tiles. A given as bf16 hi/lo planes (cp.async).
// B (expert weights) loaded as RAW FP32 via LDG, split to bf16 hi/lo in-flight,
// STS into padded SMEM planes -> no weight-prep pass needed.
// FINAL=false: epilogue GELU(acc+b1) -> hidden hi/lo planes
// FINAL=true : epilogue (acc+b2)*wgt -> out[perm] (fp32)

template<int K, int NN>
__device__ __forceinline__ void issue_stage_A(
    uint32_t sbase, int i, int tid, int row0, int rows,
    const char* gAh, const char* gAl)
{
    uint32_t st = sbase + (i & 1) * STAGE_BYTES;
    int kc = i * BK;
    // A: 2 planes x 128 rows x 4 16B-chunks = 1024 chunks, 4 per thread
#pragma unroll
    for (int s = 0; s < 4; s++) {
        int j = tid + s * NTHREADS_G;
        int plane = j >> 9, rem = j & 511;
        int m = rem >> 2, c = rem & 3;
        int mc = m < rows ? m : 0;
        const char* g = (plane ? gAl : gAh) + ((size_t)(row0 + mc) * K + kc) * 2 + c * 16;
        uint32_t d = st + (plane ? OA_L : OA_H) + m * A_STRIDE + c * 16;
        cp16(d, g, m < rows ? 16u : 0u);
    }
    cp_commit();
}

// load B fp32 tile (BK x BN) for stage i into registers: 4 float4 per thread
template<int NN>
__device__ __forceinline__ void ldg_B(
    const float* gB, int i, int tid, int n0, float4* breg)
{
    int kc = i * BK;
#pragma unroll
    for (int s = 0; s < 4; s++) {
        int j = tid + s * NTHREADS_G;   // 0..1023
        int kr = j >> 5, c = j & 31;    // row 0..31, float4-col 0..31
        breg[s] = __ldg((const float4*)(gB + (size_t)(kc + kr) * NN + n0 + c * 4));
    }
}

// convert + store B planes for stage i
__device__ __forceinline__ void sts_B(
    uint32_t sbase, int i, int tid, const float4* breg)
{
    uint32_t st = sbase + (i & 1) * STAGE_BYTES;
#pragma unroll
    for (int s = 0; s < 4; s++) {
        int j = tid + s * NTHREADS_G;
        int kr = j >> 5, c = j & 31;
        uint2 hi, lo;
        split4(breg[s], hi, lo);
        uint32_t off = kr * B_STRIDE + c * 8;
        sts64(st + OB_H + off, hi.x, hi.y);
        sts64(st + OB_L + off, lo.x, lo.y);
    }
}

template<int K, int NN, bool FINAL>
__global__ __launch_bounds__(NTHREADS_G, 1) void gemm_mma_kernel(
    const __nv_bfloat16* __restrict__ Ah, const __nv_bfloat16* __restrict__ Al,
    const float* __restrict__ Wsrc,
    const float* __restrict__ bsrc, float* __restrict__ out)
{
    extern __shared__ char smem[];
    int t = blockIdx.x;
    if (t >= g_num_tiles) return;
    int e    = g_tile_e[t];
    int row0 = g_tile_row[t];
    int rows = g_tile_rows[t];
    int n0   = blockIdx.y * BN;

    const char* gAh = (const char*)Ah;
    const char* gAl = (const char*)Al;
    const float* gB = Wsrc + (size_t)e * K * NN;
    const float* bpn = bsrc + (size_t)e * NN + n0;

    uint32_t sbase = smem_u32(smem);
    int tid = threadIdx.x, lane = tid & 31, wid = tid >> 5;
    int warp_m = wid & 3;      // 4 warps in M -> 32 rows each
    int warp_n = wid >> 2;     // 2 warps in N -> 64 cols each

    const int niter = K / BK;

    float acc[2][8][4];
#pragma unroll
    for (int mt = 0; mt < 2; mt++)
#pragma unroll
        for (int nt = 0; nt < 8; nt++)
#pragma unroll
            for (int q = 0; q < 4; q++) acc[mt][nt][q] = 0.0f;

    int lr16 = lane & 15, lc8 = lane >> 4;

    float4 breg[4];
    // prologue: stage 0
    issue_stage_A<K, NN>(sbase, 0, tid, row0, rows, gAh, gAl);
    ldg_B<NN>(gB, 0, tid, n0, breg);
    asm volatile("cp.async.wait_group 0;" ::: "memory");
    sts_B(sbase, 0, tid, breg);
    __syncthreads();

    for (int i = 0; i < niter; i++) {
        bool more = (i + 1 < niter);
        if (more) {
            issue_stage_A<K, NN>(sbase, i + 1, tid, row0, rows, gAh, gAl);
            ldg_B<NN>(gB, i + 1, tid, n0, breg);
        }

        uint32_t st = sbase + (i & 1) * STAGE_BYTES;
#pragma unroll
        for (int ks = 0; ks < 2; ks++) {
            uint32_t ah[2][4], al[2][4], bh[4][4], bl[4][4];
#pragma unroll
            for (int mt = 0; mt < 2; mt++) {
                uint32_t arow = warp_m * 32 + mt * 16 + lr16;
                uint32_t aoff = arow * A_STRIDE + ks * 32 + lc8 * 16;
                ldsm_x4(ah[mt], st + OA_H + aoff);
                ldsm_x4(al[mt], st + OA_L + aoff);
            }
#pragma unroll
            for (int np = 0; np < 4; np++) {
                uint32_t brow = ks * 16 + lr16;
                uint32_t bcol = warp_n * 64 + np * 16 + lc8 * 8;
                uint32_t boff = brow * B_STRIDE + bcol * 2;
                ldsm_x4_t(bh[np], st + OB_H + boff);
                ldsm_x4_t(bl[np], st + OB_L + boff);
            }
#pragma unroll
            for (int mt = 0; mt < 2; mt++)
#pragma unroll
                for (int nt = 0; nt < 8; nt++) {
                    const uint32_t* bq_h = &bh[nt >> 1][(nt & 1) * 2];
                    const uint32_t* bq_l = &bl[nt >> 1][(nt & 1) * 2];
                    mma_bf16(acc[mt][nt], ah[mt], bq_h);
                    mma_bf16(acc[mt][nt], al[mt], bq_h);
                    mma_bf16(acc[mt][nt], ah[mt], bq_l);
                }
        }

        if (more) {
            sts_B(sbase, i + 1, tid, breg);
            asm volatile("cp.async.wait_group 0;" ::: "memory");
            __syncthreads();
        }
    }

    // ---- epilogue ----
    int lr = lane >> 2, lc = (lane & 3) * 2;
    int   tokr[2][2];
    float wr[2][2];
#pragma unroll
    for (int mt = 0; mt < 2; mt++)
#pragma unroll
        for (int hh = 0; hh < 2; hh++) {
            int ml = warp_m * 32 + mt * 16 + lr + hh * 8;
            if (FINAL && ml < rows) {
                int tok = g_perm[row0 + ml];
                tokr[mt][hh] = tok;
                wr[mt][hh]   = g_wgt[tok];
            } else {
                tokr[mt][hh] = 0; wr[mt][hh] = 0.f;
            }
        }

#pragma unroll
    for (int nt = 0; nt < 8; nt++) {
        int ncl = warp_n * 64 + nt * 8 + lc;
        float b0 = __ldg(bpn + ncl), b1 = __ldg(bpn + ncl + 1);
#pragma unroll
        for (int mt = 0; mt < 2; mt++)
#pragma unroll
            for (int hh = 0; hh < 2; hh++) {
                int ml = warp_m * 32 + mt * 16 + lr + hh * 8;
                if (ml >= rows) continue;
                float v0 = acc[mt][nt][2 * hh]     + b0;
                float v1 = acc[mt][nt][2 * hh + 1] + b1;
                if (FINAL) {
                    float w = wr[mt][hh];
                    float2* o = (float2*)(out + (size_t)tokr[mt][hh] * NN + n0 + ncl);
                    *o = make_float2(v0 * w, v1 * w);
                } else {
                    float g0 = gelu_erf(v0), g1 = gelu_erf(v1);
                    float h0 = __bfloat162float(__float2bfloat16_rn(g0));
                    float h1 = __bfloat162float(__float2bfloat16_rn(g1));
                    size_t idx = (size_t)(row0 + ml) * NN + n0 + ncl;
                    *(uint32_t*)(g_hh + idx) = pack_bf2(h0, h1);
                    *(uint32_t*)(g_hl + idx) = pack_bf2(g0 - h0, g1 - h1);
                }
            }
    }
}

// ---------------- launch -----------------------------------------------------
extern "C" void kernel_launch(void* const* d_in, const int* in_sizes, int n_in,
                              void* d_out, int out_size)
{
    const float* h  = (const float*)d_in[0];   // (B,S,D)
    const float* rw = (const float*)d_in[1];   // (D,E)
    const float* w1 = (const float*)d_in[2];   // (E,D,F)
    const float* b1 = (const float*)d_in[3];   // (E,F)
    const float* w2 = (const float*)d_in[4];   // (E,F,D)
    const float* b2 = (const float*)d_in[5];   // (E,D)
    float* out = (float*)d_out;                // (B,S,D)

    cudaFuncSetAttribute(gemm_mma_kernel<DD, FF, false>,
                         cudaFuncAttributeMaxDynamicSharedMemorySize, SMEM_GEMM);
    cudaFuncSetAttribute(gemm_mma_kernel<FF, DD, true>,
                         cudaFuncAttributeMaxDynamicSharedMemorySize, SMEM_GEMM);
    cudaFuncSetAttribute(router_kernel,
                         cudaFuncAttributeMaxDynamicSharedMemorySize, SMEM_RT);

    __nv_bfloat16 *xh, *xl, *hh, *hl;
    cudaGetSymbolAddress((void**)&xh, g_xh);
    cudaGetSymbolAddress((void**)&xl, g_xl);
    cudaGetSymbolAddress((void**)&hh, g_hh);
    cudaGetSymbolAddress((void**)&hl, g_hl);

    zero_kernel<<<1, 32>>>();
    router_kernel<<<NTOK / RT_WARPS, 512, SMEM_RT>>>(h, rw);
    plan_kernel<<<1, 32>>>();
    scatter_gather_kernel<<<NTOK, 256>>>(h);

    gemm_mma_kernel<DD, FF, false><<<dim3(MAX_TILES, FF / BN), NTHREADS_G, SMEM_GEMM>>>(
        xh, xl, w1, b1, nullptr);
    gemm_mma_kernel<FF, DD, true><<<dim3(MAX_TILES, DD / BN), NTHREADS_G, SMEM_GEMM>>>(
        hh, hl, w2, b2, out);
}

// round 10
// speedup vs baseline: 1.1482x; 1.1482x over previous
#include <cuda_runtime.h>
#include <cuda_bf16.h>
#include <math.h>
#include <stdint.h>

// Problem constants
#define NB 2
#define NS 2048
#define NTOK (NB * NS)          // 4096
#define DD 1024
#define FF 2048
#define NE 16

// GEMM tiling
#define BM 128
#define BN 128
#define BK 32
#define NTHREADS_G 128          // 4 warps (2 M x 2 N), 64x64 warp tiles
#define GRID_X 48               // = NTOK/BM + NE (exact tile-count bound)

// SMEM stage layout (padded, bank-conflict-free for ldmatrix)
#define A_STRIDE 80             // 32 bf16 = 64B data + 16B pad
#define B_STRIDE 272            // 128 bf16 = 256B data + 16B pad
#define OA_H 0
#define OA_L (OA_H + BM * A_STRIDE)            // 10240
#define OB_H (OA_L + BM * A_STRIDE)            // 20480
#define OB_L (OB_H + BK * B_STRIDE)            // 29184
#define STAGE_BYTES (OB_L + BK * B_STRIDE)     // 37888
#define SMEM_GEMM (2 * STAGE_BYTES)            // 75776

// Router
#define RT_WARPS 16
#define SMEM_RT (DD * 17 * 4)   // 69632

// ---------------- device scratch (static globals: allocation-free) ----------
__device__ __nv_bfloat16 g_xh[NTOK * DD];      // gathered tokens hi (8 MB)
__device__ __nv_bfloat16 g_xl[NTOK * DD];      // lo
__device__ __nv_bfloat16 g_hh[NTOK * FF];      // hidden hi (16 MB)
__device__ __nv_bfloat16 g_hl[NTOK * FF];      // lo
__device__ int   g_assign[NTOK];
__device__ float g_wgt[NTOK];
__device__ int   g_perm[NTOK];
__device__ int   g_counts[NE];
__device__ int   g_cursor[NE];
__device__ int   g_row_start[NE];
__device__ int   g_tile_e[GRID_X];
__device__ int   g_tile_row[GRID_X];
__device__ int   g_tile_rows[GRID_X];
__device__ int   g_num_tiles;

// ---------------- helpers ----------------------------------------------------
__device__ __forceinline__ uint32_t smem_u32(const void* p) {
    uint32_t a;
    asm("{ .reg .u64 t; cvta.to.shared.u64 t, %1; cvt.u32.u64 %0, t; }" : "=r"(a) : "l"(p));
    return a;
}
__device__ __forceinline__ void cp16(uint32_t dst, const void* src, uint32_t sz) {
    asm volatile("cp.async.cg.shared.global [%0], [%1], 16, %2;"
                 :: "r"(dst), "l"(src), "r"(sz) : "memory");
}
__device__ __forceinline__ void cp_commit() {
    asm volatile("cp.async.commit_group;" ::: "memory");
}
__device__ __forceinline__ void ldsm_x4(uint32_t* r, uint32_t addr) {
    asm volatile("ldmatrix.sync.aligned.m8n8.x4.shared.b16 {%0,%1,%2,%3}, [%4];"
                 : "=r"(r[0]), "=r"(r[1]), "=r"(r[2]), "=r"(r[3]) : "r"(addr));
}
__device__ __forceinline__ void ldsm_x4_t(uint32_t* r, uint32_t addr) {
    asm volatile("ldmatrix.sync.aligned.m8n8.x4.trans.shared.b16 {%0,%1,%2,%3}, [%4];"
                 : "=r"(r[0]), "=r"(r[1]), "=r"(r[2]), "=r"(r[3]) : "r"(addr));
}
__device__ __forceinline__ void mma_bf16(float* d, const uint32_t* a, const uint32_t* b) {
    asm volatile("mma.sync.aligned.m16n8k16.row.col.f32.bf16.bf16.f32 "
                 "{%0,%1,%2,%3}, {%4,%5,%6,%7}, {%8,%9}, {%0,%1,%2,%3};"
                 : "+f"(d[0]), "+f"(d[1]), "+f"(d[2]), "+f"(d[3])
                 : "r"(a[0]), "r"(a[1]), "r"(a[2]), "r"(a[3]), "r"(b[0]), "r"(b[1]));
}
__device__ __forceinline__ uint32_t pack_bf2(float a, float b) {
    __nv_bfloat162 t = __floats2bfloat162_rn(a, b);
    return *reinterpret_cast<uint32_t*>(&t);
}
__device__ __forceinline__ void sts64(uint32_t addr, uint32_t x, uint32_t y) {
    asm volatile("st.shared.v2.b32 [%0], {%1, %2};" :: "r"(addr), "r"(x), "r"(y) : "memory");
}
__device__ __forceinline__ float gelu_erf(float x) {
    return 0.5f * x * (1.0f + erff(x * 0.70710678118654752440f));
}
// split float4 -> hi uint2 / lo uint2
__device__ __forceinline__ void split4(float4 v, uint2& hi, uint2& lo) {
    float hx = __bfloat162float(__float2bfloat16_rn(v.x));
    float hy = __bfloat162float(__float2bfloat16_rn(v.y));
    float hz = __bfloat162float(__float2bfloat16_rn(v.z));
    float hw = __bfloat162float(__float2bfloat16_rn(v.w));
    hi = make_uint2(pack_bf2(hx, hy), pack_bf2(hz, hw));
    lo = make_uint2(pack_bf2(v.x - hx, v.y - hy), pack_bf2(v.z - hz, v.w - hw));
}

// ---------------- routing ----------------------------------------------------
__global__ void zero_kernel() {
    int t = threadIdx.x;
    if (t < NE) { g_counts[t] = 0; g_cursor[t] = 0; }
}

// router: rw cached in smem (stride 17 -> conflict-free), 16 tokens/block
__global__ __launch_bounds__(512) void router_kernel(
    const float* __restrict__ h, const float* __restrict__ rw)
{
    extern __shared__ float srw[];   // [DD][17]
    int tid = threadIdx.x, lane = tid & 31, wid = tid >> 5;
    for (int i = tid; i < DD * NE; i += 512)
        srw[(i >> 4) * 17 + (i & 15)] = rw[i];
    __syncthreads();

    int tok = blockIdx.x * RT_WARPS + wid;
    const float* x = h + (size_t)tok * DD;
    float acc[NE];
#pragma unroll
    for (int e = 0; e < NE; e++) acc[e] = 0.0f;
    for (int d = lane; d < DD; d += 32) {
        float xv = x[d];
        const float* r = &srw[d * 17];
#pragma unroll
        for (int e = 0; e < NE; e++) acc[e] += xv * r[e];
    }
#pragma unroll
    for (int e = 0; e < NE; e++)
#pragma unroll
        for (int o = 16; o > 0; o >>= 1)
            acc[e] += __shfl_down_sync(0xFFFFFFFFu, acc[e], o);
    if (lane == 0) {
        int best = 0; float bv = acc[0];
#pragma unroll
        for (int e = 1; e < NE; e++)
            if (acc[e] > bv) { bv = acc[e]; best = e; }
        g_assign[tok] = best;
        g_wgt[tok]    = 1.0f / (1.0f + expf(-bv));
        atomicAdd(&g_counts[best], 1);
    }
}

__global__ void plan_kernel() {
    if (threadIdx.x != 0) return;
    int off = 0, t = 0;
    for (int e = 0; e < NE; e++) {
        g_row_start[e] = off;
        int c = g_counts[e];
        for (int r = 0; r < c; r += BM) {
            g_tile_e[t] = e; g_tile_row[t] = off + r;
            g_tile_rows[t] = min(BM, c - r); t++;
        }
        off += c;
    }
    g_num_tiles = t;
}

// merged scatter+gather: block per token; computes sorted position, writes perm
// and the bf16 hi/lo planes of the token row.
__global__ __launch_bounds__(256) void scatter_gather_kernel(const float* __restrict__ h) {
    __shared__ int spos;
    int tok = blockIdx.x;
    if (threadIdx.x == 0) {
        int e = g_assign[tok];
        int p = g_row_start[e] + atomicAdd(&g_cursor[e], 1);
        g_perm[p] = tok;
        spos = p;
    }
    __syncthreads();
    int pos = spos;
    const float4* src = (const float4*)(h + (size_t)tok * DD);
    uint2* dh = (uint2*)(g_xh + (size_t)pos * DD);
    uint2* dl = (uint2*)(g_xl + (size_t)pos * DD);
    float4 v = src[threadIdx.x];
    uint2 hi, lo;
    split4(v, hi, lo);
    dh[threadIdx.x] = hi;
    dl[threadIdx.x] = lo;
}

// ---------------- split-bf16 mma.sync grouped GEMM ---------------------------
// 4 warps (2x2), 64x64 warp tiles. A given as bf16 hi/lo planes (cp.async).
// B (expert weights) loaded as RAW FP32 via LDG, split to bf16 hi/lo in-flight,
// STS into padded SMEM planes -> no weight-prep pass needed.
// MMA issue is TERM-MAJOR (all Ah*Bh, then Al*Bh, then Ah*Bl) so consecutive
// MMAs never share an accumulator quad -> no RAW-chain stalls.
// FINAL=false: epilogue GELU(acc+b1) -> hidden hi/lo planes
// FINAL=true : epilogue (acc+b2)*wgt -> out[perm] (fp32)

template<int K, int NN>
__device__ __forceinline__ void issue_stage_A(
    uint32_t sbase, int i, int tid, int row0, int rows,
    const char* gAh, const char* gAl)
{
    uint32_t st = sbase + (i & 1) * STAGE_BYTES;
    int kc = i * BK;
    // A: 2 planes x 128 rows x 4 16B-chunks = 1024 chunks, 8 per thread
#pragma unroll
    for (int s = 0; s < 8; s++) {
        int j = tid + s * NTHREADS_G;
        int plane = j >> 9, rem = j & 511;
        int m = rem >> 2, c = rem & 3;
        int mc = m < rows ? m : 0;
        const char* g = (plane ? gAl : gAh) + ((size_t)(row0 + mc) * K + kc) * 2 + c * 16;
        uint32_t d = st + (plane ? OA_L : OA_H) + m * A_STRIDE + c * 16;
        cp16(d, g, m < rows ? 16u : 0u);
    }
    cp_commit();
}

// load B fp32 tile (BK x BN) for stage i into registers: 8 float4 per thread
template<int NN>
__device__ __forceinline__ void ldg_B(
    const float* gB, int i, int tid, int n0, float4* breg)
{
    int kc = i * BK;
#pragma unroll
    for (int s = 0; s < 8; s++) {
        int j = tid + s * NTHREADS_G;   // 0..1023
        int kr = j >> 5, c = j & 31;    // row 0..31, float4-col 0..31
        breg[s] = __ldg((const float4*)(gB + (size_t)(kc + kr) * NN + n0 + c * 4));
    }
}

// convert + store B planes for stage i
__device__ __forceinline__ void sts_B(
    uint32_t sbase, int i, int tid, const float4* breg)
{
    uint32_t st = sbase + (i & 1) * STAGE_BYTES;
#pragma unroll
    for (int s = 0; s < 8; s++) {
        int j = tid + s * NTHREADS_G;
        int kr = j >> 5, c = j & 31;
        uint2 hi, lo;
        split4(breg[s], hi, lo);
        uint32_t off = kr * B_STRIDE + c * 8;
        sts64(st + OB_H + off, hi.x, hi.y);
        sts64(st + OB_L + off, lo.x, lo.y);
    }
}

template<int K, int NN, bool FINAL>
__global__ __launch_bounds__(NTHREADS_G, 1) void gemm_mma_kernel(
    const __nv_bfloat16* __restrict__ Ah, const __nv_bfloat16* __restrict__ Al,
    const float* __restrict__ Wsrc,
    const float* __restrict__ bsrc, float* __restrict__ out)
{
    extern __shared__ char smem[];
    int t = blockIdx.x;
    if (t >= g_num_tiles) return;
    int e    = g_tile_e[t];
    int row0 = g_tile_row[t];
    int rows = g_tile_rows[t];
    int n0   = blockIdx.y * BN;

    const char* gAh = (const char*)Ah;
    const char* gAl = (const char*)Al;
    const float* gB = Wsrc + (size_t)e * K * NN;
    const float* bpn = bsrc + (size_t)e * NN + n0;

    uint32_t sbase = smem_u32(smem);
    int tid = threadIdx.x, lane = tid & 31, wid = tid >> 5;
    int warp_m = wid & 1;      // 2 warps in M -> 64 rows each
    int warp_n = wid >> 1;     // 2 warps in N -> 64 cols each

    const int niter = K / BK;

    float acc[4][8][4];
#pragma unroll
    for (int mt = 0; mt < 4; mt++)
#pragma unroll
        for (int nt = 0; nt < 8; nt++)
#pragma unroll
            for (int q = 0; q < 4; q++) acc[mt][nt][q] = 0.0f;

    int lr16 = lane & 15, lc8 = lane >> 4;

    float4 breg[8];
    // prologue: stage 0
    issue_stage_A<K, NN>(sbase, 0, tid, row0, rows, gAh, gAl);
    ldg_B<NN>(gB, 0, tid, n0, breg);
    asm volatile("cp.async.wait_group 0;" ::: "memory");
    sts_B(sbase, 0, tid, breg);
    __syncthreads();

    for (int i = 0; i < niter; i++) {
        bool more = (i + 1 < niter);
        if (more) {
            issue_stage_A<K, NN>(sbase, i + 1, tid, row0, rows, gAh, gAl);
            ldg_B<NN>(gB, i + 1, tid, n0, breg);
        }

        uint32_t st = sbase + (i & 1) * STAGE_BYTES;
#pragma unroll
        for (int ks = 0; ks < 2; ks++) {
            uint32_t ah[4][4], al[4][4], bh[4][4], bl[4][4];
#pragma unroll
            for (int mt = 0; mt < 4; mt++) {
                uint32_t arow = warp_m * 64 + mt * 16 + lr16;
                uint32_t aoff = arow * A_STRIDE + ks * 32 + lc8 * 16;
                ldsm_x4(ah[mt], st + OA_H + aoff);
                ldsm_x4(al[mt], st + OA_L + aoff);
            }
#pragma unroll
            for (int np = 0; np < 4; np++) {
                uint32_t brow = ks * 16 + lr16;
                uint32_t bcol = warp_n * 64 + np * 16 + lc8 * 8;
                uint32_t boff = brow * B_STRIDE + bcol * 2;
                ldsm_x4_t(bh[np], st + OB_H + boff);
                ldsm_x4_t(bl[np], st + OB_L + boff);
            }
            // term-major: consecutive MMAs never hit the same accumulator
#pragma unroll
            for (int mt = 0; mt < 4; mt++)
#pragma unroll
                for (int nt = 0; nt < 8; nt++)
                    mma_bf16(acc[mt][nt], ah[mt], &bh[nt >> 1][(nt & 1) * 2]);
#pragma unroll
            for (int mt = 0; mt < 4; mt++)
#pragma unroll
                for (int nt = 0; nt < 8; nt++)
                    mma_bf16(acc[mt][nt], al[mt], &bh[nt >> 1][(nt & 1) * 2]);
#pragma unroll
            for (int mt = 0; mt < 4; mt++)
#pragma unroll
                for (int nt = 0; nt < 8; nt++)
                    mma_bf16(acc[mt][nt], ah[mt], &bl[nt >> 1][(nt & 1) * 2]);
        }

        if (more) {
            sts_B(sbase, i + 1, tid, breg);
            asm volatile("cp.async.wait_group 0;" ::: "memory");
            __syncthreads();
        }
    }

    // ---- epilogue ----
    int lr = lane >> 2, lc = (lane & 3) * 2;
    int   tokr[4][2];
    float wr[4][2];
#pragma unroll
    for (int mt = 0; mt < 4; mt++)
#pragma unroll
        for (int hh = 0; hh < 2; hh++) {
            int ml = warp_m * 64 + mt * 16 + lr + hh * 8;
            if (FINAL && ml < rows) {
                int tok = g_perm[row0 + ml];
                tokr[mt][hh] = tok;
                wr[mt][hh]   = g_wgt[tok];
            } else {
                tokr[mt][hh] = 0; wr[mt][hh] = 0.f;
            }
        }

#pragma unroll
    for (int nt = 0; nt < 8; nt++) {
        int ncl = warp_n * 64 + nt * 8 + lc;
        float b0 = __ldg(bpn + ncl), b1 = __ldg(bpn + ncl + 1);
#pragma unroll
        for (int mt = 0; mt < 4; mt++)
#pragma unroll
            for (int hh = 0; hh < 2; hh++) {
                int ml = warp_m * 64 + mt * 16 + lr + hh * 8;
                if (ml >= rows) continue;
                float v0 = acc[mt][nt][2 * hh]     + b0;
                float v1 = acc[mt][nt][2 * hh + 1] + b1;
                if (FINAL) {
                    float w = wr[mt][hh];
                    float2* o = (float2*)(out + (size_t)tokr[mt][hh] * NN + n0 + ncl);
                    *o = make_float2(v0 * w, v1 * w);
                } else {
                    float g0 = gelu_erf(v0), g1 = gelu_erf(v1);
                    float h0 = __bfloat162float(__float2bfloat16_rn(g0));
                    float h1 = __bfloat162float(__float2bfloat16_rn(g1));
                    size_t idx = (size_t)(row0 + ml) * NN + n0 + ncl;
                    *(uint32_t*)(g_hh + idx) = pack_bf2(h0, h1);
                    *(uint32_t*)(g_hl + idx) = pack_bf2(g0 - h0, g1 - h1);
                }
            }
    }
}

// ---------------- launch -----------------------------------------------------
extern "C" void kernel_launch(void* const* d_in, const int* in_sizes, int n_in,
                              void* d_out, int out_size)
{
    const float* h  = (const float*)d_in[0];   // (B,S,D)
    const float* rw = (const float*)d_in[1];   // (D,E)
    const float* w1 = (const float*)d_in[2];   // (E,D,F)
    const float* b1 = (const float*)d_in[3];   // (E,F)
    const float* w2 = (const float*)d_in[4];   // (E,F,D)
    const float* b2 = (const float*)d_in[5];   // (E,D)
    float* out = (float*)d_out;                // (B,S,D)

    cudaFuncSetAttribute(gemm_mma_kernel<DD, FF, false>,
                         cudaFuncAttributeMaxDynamicSharedMemorySize, SMEM_GEMM);
    cudaFuncSetAttribute(gemm_mma_kernel<FF, DD, true>,
                         cudaFuncAttributeMaxDynamicSharedMemorySize, SMEM_GEMM);
    cudaFuncSetAttribute(router_kernel,
                         cudaFuncAttributeMaxDynamicSharedMemorySize, SMEM_RT);

    __nv_bfloat16 *xh, *xl, *hh, *hl;
    cudaGetSymbolAddress((void**)&xh, g_xh);
    cudaGetSymbolAddress((void**)&xl, g_xl);
    cudaGetSymbolAddress((void**)&hh, g_hh);
    cudaGetSymbolAddress((void**)&hl, g_hl);

    zero_kernel<<<1, 32>>>();
    router_kernel<<<NTOK / RT_WARPS, 512, SMEM_RT>>>(h, rw);
    plan_kernel<<<1, 32>>>();
    scatter_gather_kernel<<<NTOK, 256>>>(h);

    gemm_mma_kernel<DD, FF, false><<<dim3(GRID_X, FF / BN), NTHREADS_G, SMEM_GEMM>>>(
        xh, xl, w1, b1, nullptr);
    gemm_mma_kernel<FF, DD, true><<<dim3(GRID_X, DD / BN), NTHREADS_G, SMEM_GEMM>>>(
        hh, hl, w2, b2, out);
}

// round 11
// speedup vs baseline: 2.0431x; 1.7793x over previous
#include <cuda_runtime.h>
#include <cuda_fp16.h>
#include <cuda_bf16.h>
#include <math.h>
#include <stdint.h>

// Problem constants
#define NB 2
#define NS 2048
#define NTOK (NB * NS)          // 4096
#define DD 1024
#define FF 2048
#define NE 16

// GEMM tiling
#define BM 128
#define BN 128
#define BK 32
#define NTHREADS_G 128          // 4 warps (2 M x 2 N), 64x64 warp tiles
#define GRID_X 48               // = NTOK/BM + NE (exact tile-count bound)

// SMEM stage layout (padded, bank-conflict-free for ldmatrix)
#define A_STRIDE 80             // 32 fp16 = 64B data + 16B pad
#define B_STRIDE 272            // 128 fp16 = 256B data + 16B pad
#define OA_H 0
#define OB_H (OA_H + BM * A_STRIDE)            // 10240
#define STAGE_BYTES (OB_H + BK * B_STRIDE)     // 18944
#define SMEM_GEMM (2 * STAGE_BYTES)            // 37888

// Router
#define RT_WARPS 16
#define SMEM_RT (DD * 17 * 4)   // 69632

// ---------------- device scratch (static globals: allocation-free) ----------
__device__ __half g_xh[NTOK * DD];      // gathered tokens fp16 (8 MB)
__device__ __half g_hh[NTOK * FF];      // hidden fp16 (16 MB)
__device__ int   g_assign[NTOK];
__device__ float g_wgt[NTOK];
__device__ int   g_perm[NTOK];
__device__ int   g_counts[NE];
__device__ int   g_cursor[NE];
__device__ int   g_row_start[NE];
__device__ int   g_tile_e[GRID_X];
__device__ int   g_tile_row[GRID_X];
__device__ int   g_tile_rows[GRID_X];
__device__ int   g_num_tiles;

// ---------------- helpers ----------------------------------------------------
__device__ __forceinline__ uint32_t smem_u32(const void* p) {
    uint32_t a;
    asm("{ .reg .u64 t; cvta.to.shared.u64 t, %1; cvt.u32.u64 %0, t; }" : "=r"(a) : "l"(p));
    return a;
}
__device__ __forceinline__ void cp16(uint32_t dst, const void* src, uint32_t sz) {
    asm volatile("cp.async.cg.shared.global [%0], [%1], 16, %2;"
                 :: "r"(dst), "l"(src), "r"(sz) : "memory");
}
__device__ __forceinline__ void cp_commit() {
    asm volatile("cp.async.commit_group;" ::: "memory");
}
__device__ __forceinline__ void ldsm_x4(uint32_t* r, uint32_t addr) {
    asm volatile("ldmatrix.sync.aligned.m8n8.x4.shared.b16 {%0,%1,%2,%3}, [%4];"
                 : "=r"(r[0]), "=r"(r[1]), "=r"(r[2]), "=r"(r[3]) : "r"(addr));
}
__device__ __forceinline__ void ldsm_x4_t(uint32_t* r, uint32_t addr) {
    asm volatile("ldmatrix.sync.aligned.m8n8.x4.trans.shared.b16 {%0,%1,%2,%3}, [%4];"
                 : "=r"(r[0]), "=r"(r[1]), "=r"(r[2]), "=r"(r[3]) : "r"(addr));
}
__device__ __forceinline__ void mma_f16(float* d, const uint32_t* a, const uint32_t* b) {
    asm volatile("mma.sync.aligned.m16n8k16.row.col.f32.f16.f16.f32 "
                 "{%0,%1,%2,%3}, {%4,%5,%6,%7}, {%8,%9}, {%0,%1,%2,%3};"
                 : "+f"(d[0]), "+f"(d[1]), "+f"(d[2]), "+f"(d[3])
                 : "r"(a[0]), "r"(a[1]), "r"(a[2]), "r"(a[3]), "r"(b[0]), "r"(b[1]));
}
__device__ __forceinline__ uint32_t pack_h2(float a, float b) {
    __half2 t = __floats2half2_rn(a, b);
    return *reinterpret_cast<uint32_t*>(&t);
}
__device__ __forceinline__ void sts64(uint32_t addr, uint32_t x, uint32_t y) {
    asm volatile("st.shared.v2.b32 [%0], {%1, %2};" :: "r"(addr), "r"(x), "r"(y) : "memory");
}
__device__ __forceinline__ float gelu_erf(float x) {
    return 0.5f * x * (1.0f + erff(x * 0.70710678118654752440f));
}
// convert float4 -> 4 fp16 packed in uint2
__device__ __forceinline__ uint2 cvt4(float4 v) {
    return make_uint2(pack_h2(v.x, v.y), pack_h2(v.z, v.w));
}

// ---------------- routing ----------------------------------------------------
__global__ void zero_kernel() {
    int t = threadIdx.x;
    if (t < NE) { g_counts[t] = 0; g_cursor[t] = 0; }
}

// router: rw cached in smem (stride 17 -> conflict-free), 16 tokens/block
__global__ __launch_bounds__(512) void router_kernel(
    const float* __restrict__ h, const float* __restrict__ rw)
{
    extern __shared__ float srw[];   // [DD][17]
    int tid = threadIdx.x, lane = tid & 31, wid = tid >> 5;
    for (int i = tid; i < DD * NE; i += 512)
        srw[(i >> 4) * 17 + (i & 15)] = rw[i];
    __syncthreads();

    int tok = blockIdx.x * RT_WARPS + wid;
    const float* x = h + (size_t)tok * DD;
    float acc[NE];
#pragma unroll
    for (int e = 0; e < NE; e++) acc[e] = 0.0f;
    for (int d = lane; d < DD; d += 32) {
        float xv = x[d];
        const float* r = &srw[d * 17];
#pragma unroll
        for (int e = 0; e < NE; e++) acc[e] += xv * r[e];
    }
#pragma unroll
    for (int e = 0; e < NE; e++)
#pragma unroll
        for (int o = 16; o > 0; o >>= 1)
            acc[e] += __shfl_down_sync(0xFFFFFFFFu, acc[e], o);
    if (lane == 0) {
        int best = 0; float bv = acc[0];
#pragma unroll
        for (int e = 1; e < NE; e++)
            if (acc[e] > bv) { bv = acc[e]; best = e; }
        g_assign[tok] = best;
        g_wgt[tok]    = 1.0f / (1.0f + expf(-bv));
        atomicAdd(&g_counts[best], 1);
    }
}

__global__ void plan_kernel() {
    if (threadIdx.x != 0) return;
    int off = 0, t = 0;
    for (int e = 0; e < NE; e++) {
        g_row_start[e] = off;
        int c = g_counts[e];
        for (int r = 0; r < c; r += BM) {
            g_tile_e[t] = e; g_tile_row[t] = off + r;
            g_tile_rows[t] = min(BM, c - r); t++;
        }
        off += c;
    }
    g_num_tiles = t;
}

// merged scatter+gather: block per token; computes sorted position, writes perm
// and the fp16 token row.
__global__ __launch_bounds__(256) void scatter_gather_kernel(const float* __restrict__ h) {
    __shared__ int spos;
    int tok = blockIdx.x;
    if (threadIdx.x == 0) {
        int e = g_assign[tok];
        int p = g_row_start[e] + atomicAdd(&g_cursor[e], 1);
        g_perm[p] = tok;
        spos = p;
    }
    __syncthreads();
    int pos = spos;
    const float4* src = (const float4*)(h + (size_t)tok * DD);
    uint2* dh = (uint2*)(g_xh + (size_t)pos * DD);
    dh[threadIdx.x] = cvt4(src[threadIdx.x]);
}

// ---------------- fp16 mma.sync grouped GEMM ---------------------------------
// 4 warps (2x2), 64x64 warp tiles. A given as fp16 plane (cp.async).
// B (expert weights) loaded as RAW FP32 via LDG, converted to fp16 in-flight,
// STS into padded SMEM plane -> no weight-prep pass needed.
// FINAL=false: epilogue GELU(acc+b1) -> hidden fp16
// FINAL=true : epilogue (acc+b2)*wgt -> out[perm] (fp32)

template<int K, int NN>
__device__ __forceinline__ void issue_stage_A(
    uint32_t sbase, int i, int tid, int row0, int rows, const char* gA)
{
    uint32_t st = sbase + (i & 1) * STAGE_BYTES;
    int kc = i * BK;
    // A: 128 rows x 4 16B-chunks = 512 chunks, 4 per thread
#pragma unroll
    for (int s = 0; s < 4; s++) {
        int j = tid + s * NTHREADS_G;
        int m = j >> 2, c = j & 3;
        int mc = m < rows ? m : 0;
        const char* g = gA + ((size_t)(row0 + mc) * K + kc) * 2 + c * 16;
        uint32_t d = st + OA_H + m * A_STRIDE + c * 16;
        cp16(d, g, m < rows ? 16u : 0u);
    }
    cp_commit();
}

// load B fp32 tile (BK x BN) for stage i into registers: 8 float4 per thread
template<int NN>
__device__ __forceinline__ void ldg_B(
    const float* gB, int i, int tid, int n0, float4* breg)
{
    int kc = i * BK;
#pragma unroll
    for (int s = 0; s < 8; s++) {
        int j = tid + s * NTHREADS_G;   // 0..1023
        int kr = j >> 5, c = j & 31;    // row 0..31, float4-col 0..31
        breg[s] = __ldg((const float4*)(gB + (size_t)(kc + kr) * NN + n0 + c * 4));
    }
}

// convert + store B fp16 plane for stage i
__device__ __forceinline__ void sts_B(
    uint32_t sbase, int i, int tid, const float4* breg)
{
    uint32_t st = sbase + (i & 1) * STAGE_BYTES;
#pragma unroll
    for (int s = 0; s < 8; s++) {
        int j = tid + s * NTHREADS_G;
        int kr = j >> 5, c = j & 31;
        uint2 hv = cvt4(breg[s]);
        uint32_t off = kr * B_STRIDE + c * 8;
        sts64(st + OB_H + off, hv.x, hv.y);
    }
}

template<int K, int NN, bool FINAL>
__global__ __launch_bounds__(NTHREADS_G, 1) void gemm_mma_kernel(
    const __half* __restrict__ Ain,
    const float* __restrict__ Wsrc,
    const float* __restrict__ bsrc, float* __restrict__ out)
{
    extern __shared__ char smem[];
    int t = blockIdx.x;
    if (t >= g_num_tiles) return;
    int e    = g_tile_e[t];
    int row0 = g_tile_row[t];
    int rows = g_tile_rows[t];
    int n0   = blockIdx.y * BN;

    const char* gA = (const char*)Ain;
    const float* gB = Wsrc + (size_t)e * K * NN;
    const float* bpn = bsrc + (size_t)e * NN + n0;

    uint32_t sbase = smem_u32(smem);
    int tid = threadIdx.x, lane = tid & 31, wid = tid >> 5;
    int warp_m = wid & 1;      // 2 warps in M -> 64 rows each
    int warp_n = wid >> 1;     // 2 warps in N -> 64 cols each

    const int niter = K / BK;

    float acc[4][8][4];
#pragma unroll
    for (int mt = 0; mt < 4; mt++)
#pragma unroll
        for (int nt = 0; nt < 8; nt++)
#pragma unroll
            for (int q = 0; q < 4; q++) acc[mt][nt][q] = 0.0f;

    int lr16 = lane & 15, lc8 = lane >> 4;

    float4 breg[8];
    // prologue: stage 0
    issue_stage_A<K, NN>(sbase, 0, tid, row0, rows, gA);
    ldg_B<NN>(gB, 0, tid, n0, breg);
    asm volatile("cp.async.wait_group 0;" ::: "memory");
    sts_B(sbase, 0, tid, breg);
    __syncthreads();

    for (int i = 0; i < niter; i++) {
        bool more = (i + 1 < niter);
        if (more) {
            issue_stage_A<K, NN>(sbase, i + 1, tid, row0, rows, gA);
            ldg_B<NN>(gB, i + 1, tid, n0, breg);
        }

        uint32_t st = sbase + (i & 1) * STAGE_BYTES;
#pragma unroll
        for (int ks = 0; ks < 2; ks++) {
            uint32_t ah[4][4], bh[4][4];
#pragma unroll
            for (int mt = 0; mt < 4; mt++) {
                uint32_t arow = warp_m * 64 + mt * 16 + lr16;
                ldsm_x4(ah[mt], st + OA_H + arow * A_STRIDE + ks * 32 + lc8 * 16);
            }
#pragma unroll
            for (int np = 0; np < 4; np++) {
                uint32_t brow = ks * 16 + lr16;
                uint32_t bcol = warp_n * 64 + np * 16 + lc8 * 8;
                ldsm_x4_t(bh[np], st + OB_H + brow * B_STRIDE + bcol * 2);
            }
#pragma unroll
            for (int mt = 0; mt < 4; mt++)
#pragma unroll
                for (int nt = 0; nt < 8; nt++)
                    mma_f16(acc[mt][nt], ah[mt], &bh[nt >> 1][(nt & 1) * 2]);
        }

        if (more) {
            sts_B(sbase, i + 1, tid, breg);
            asm volatile("cp.async.wait_group 0;" ::: "memory");
            __syncthreads();
        }
    }

    // ---- epilogue ----
    int lr = lane >> 2, lc = (lane & 3) * 2;
    int   tokr[4][2];
    float wr[4][2];
#pragma unroll
    for (int mt = 0; mt < 4; mt++)
#pragma unroll
        for (int hh = 0; hh < 2; hh++) {
            int ml = warp_m * 64 + mt * 16 + lr + hh * 8;
            if (FINAL && ml < rows) {
                int tok = g_perm[row0 + ml];
                tokr[mt][hh] = tok;
                wr[mt][hh]   = g_wgt[tok];
            } else {
                tokr[mt][hh] = 0; wr[mt][hh] = 0.f;
            }
        }

#pragma unroll
    for (int nt = 0; nt < 8; nt++) {
        int ncl = warp_n * 64 + nt * 8 + lc;
        float b0 = __ldg(bpn + ncl), b1 = __ldg(bpn + ncl + 1);
#pragma unroll
        for (int mt = 0; mt < 4; mt++)
#pragma unroll
            for (int hh = 0; hh < 2; hh++) {
                int ml = warp_m * 64 + mt * 16 + lr + hh * 8;
                if (ml >= rows) continue;
                float v0 = acc[mt][nt][2 * hh]     + b0;
                float v1 = acc[mt][nt][2 * hh + 1] + b1;
                if (FINAL) {
                    float w = wr[mt][hh];
                    float2* o = (float2*)(out + (size_t)tokr[mt][hh] * NN + n0 + ncl);
                    *o = make_float2(v0 * w, v1 * w);
                } else {
                    float g0 = gelu_erf(v0), g1 = gelu_erf(v1);
                    size_t idx = (size_t)(row0 + ml) * NN + n0 + ncl;
                    *(uint32_t*)(g_hh + idx) = pack_h2(g0, g1);
                }
            }
    }
}

// ---------------- launch -----------------------------------------------------
extern "C" void kernel_launch(void* const* d_in, const int* in_sizes, int n_in,
                              void* d_out, int out_size)
{
    const float* h  = (const float*)d_in[0];   // (B,S,D)
    const float* rw = (const float*)d_in[1];   // (D,E)
    const float* w1 = (const float*)d_in[2];   // (E,D,F)
    const float* b1 = (const float*)d_in[3];   // (E,F)
    const float* w2 = (const float*)d_in[4];   // (E,F,D)
    const float* b2 = (const float*)d_in[5];   // (E,D)
    float* out = (float*)d_out;                // (B,S,D)

    cudaFuncSetAttribute(gemm_mma_kernel<DD, FF, false>,
                         cudaFuncAttributeMaxDynamicSharedMemorySize, SMEM_GEMM);
    cudaFuncSetAttribute(gemm_mma_kernel<FF, DD, true>,
                         cudaFuncAttributeMaxDynamicSharedMemorySize, SMEM_GEMM);
    cudaFuncSetAttribute(router_kernel,
                         cudaFuncAttributeMaxDynamicSharedMemorySize, SMEM_RT);

    __half *xh, *hh;
    cudaGetSymbolAddress((void**)&xh, g_xh);
    cudaGetSymbolAddress((void**)&hh, g_hh);

    zero_kernel<<<1, 32>>>();
    router_kernel<<<NTOK / RT_WARPS, 512, SMEM_RT>>>(h, rw);
    plan_kernel<<<1, 32>>>();
    scatter_gather_kernel<<<NTOK, 256>>>(h);

    gemm_mma_kernel<DD, FF, false><<<dim3(GRID_X, FF / BN), NTHREADS_G, SMEM_GEMM>>>(
        xh, w1, b1, nullptr);
    gemm_mma_kernel<FF, DD, true><<<dim3(GRID_X, DD / BN), NTHREADS_G, SMEM_GEMM>>>(
        hh, w2, b2, out);
}

// round 12
// speedup vs baseline: 2.5310x; 1.2388x over previous
#include <cuda_runtime.h>
#include <cuda_fp16.h>
#include <math.h>
#include <stdint.h>

// Problem constants
#define NB 2
#define NS 2048
#define NTOK (NB * NS)          // 4096
#define DD 1024
#define FF 2048
#define NE 16

// GEMM tiling
#define BM 128
#define BN 64
#define BK 64
#define NTHREADS_G 128          // 4 warps (2 M x 2 N), 64x32 warp tiles
#define GRID_X 48               // = NTOK/BM + NE (exact tile-count bound)

// SMEM stage layout (padded, bank-conflict-free for ldmatrix)
#define A_STRIDE 144            // 64 fp16 = 128B data + 16B pad
#define B_STRIDE 144            // 64 fp16 = 128B data + 16B pad
#define OA_H 0
#define OB_H (OA_H + BM * A_STRIDE)            // 18432
#define STAGE_BYTES (OB_H + BK * B_STRIDE)     // 27648
#define SMEM_GEMM (2 * STAGE_BYTES)            // 55296

// Router
#define RT_WARPS 16
#define RT_STRIDE 20
#define SMEM_RT (DD * RT_STRIDE * 4)   // 81920

// ---------------- device scratch (static globals: allocation-free) ----------
__device__ __half g_xh[NTOK * DD];      // gathered tokens fp16 (8 MB)
__device__ __half g_hh[NTOK * FF];      // hidden fp16 (16 MB)
__device__ int   g_assign[NTOK];
__device__ float g_wgt[NTOK];
__device__ int   g_perm[NTOK];
__device__ int   g_counts[NE];
__device__ int   g_cursor[NE];
__device__ int   g_row_start[NE];
__device__ int   g_tile_e[GRID_X];
__device__ int   g_tile_row[GRID_X];
__device__ int   g_tile_rows[GRID_X];
__device__ int   g_num_tiles;

// ---------------- helpers ----------------------------------------------------
__device__ __forceinline__ uint32_t smem_u32(const void* p) {
    uint32_t a;
    asm("{ .reg .u64 t; cvta.to.shared.u64 t, %1; cvt.u32.u64 %0, t; }" : "=r"(a) : "l"(p));
    return a;
}
__device__ __forceinline__ void cp16(uint32_t dst, const void* src, uint32_t sz) {
    asm volatile("cp.async.cg.shared.global [%0], [%1], 16, %2;"
                 :: "r"(dst), "l"(src), "r"(sz) : "memory");
}
__device__ __forceinline__ void cp_commit() {
    asm volatile("cp.async.commit_group;" ::: "memory");
}
__device__ __forceinline__ void ldsm_x4(uint32_t* r, uint32_t addr) {
    asm volatile("ldmatrix.sync.aligned.m8n8.x4.shared.b16 {%0,%1,%2,%3}, [%4];"
                 : "=r"(r[0]), "=r"(r[1]), "=r"(r[2]), "=r"(r[3]) : "r"(addr));
}
__device__ __forceinline__ void ldsm_x4_t(uint32_t* r, uint32_t addr) {
    asm volatile("ldmatrix.sync.aligned.m8n8.x4.trans.shared.b16 {%0,%1,%2,%3}, [%4];"
                 : "=r"(r[0]), "=r"(r[1]), "=r"(r[2]), "=r"(r[3]) : "r"(addr));
}
__device__ __forceinline__ void mma_f16(float* d, const uint32_t* a, const uint32_t* b) {
    asm volatile("mma.sync.aligned.m16n8k16.row.col.f32.f16.f16.f32 "
                 "{%0,%1,%2,%3}, {%4,%5,%6,%7}, {%8,%9}, {%0,%1,%2,%3};"
                 : "+f"(d[0]), "+f"(d[1]), "+f"(d[2]), "+f"(d[3])
                 : "r"(a[0]), "r"(a[1]), "r"(a[2]), "r"(a[3]), "r"(b[0]), "r"(b[1]));
}
__device__ __forceinline__ uint32_t pack_h2(float a, float b) {
    __half2 t = __floats2half2_rn(a, b);
    return *reinterpret_cast<uint32_t*>(&t);
}
__device__ __forceinline__ void sts64(uint32_t addr, uint32_t x, uint32_t y) {
    asm volatile("st.shared.v2.b32 [%0], {%1, %2};" :: "r"(addr), "r"(x), "r"(y) : "memory");
}
__device__ __forceinline__ float gelu_erf(float x) {
    return 0.5f * x * (1.0f + erff(x * 0.70710678118654752440f));
}
__device__ __forceinline__ uint2 cvt4(float4 v) {
    return make_uint2(pack_h2(v.x, v.y), pack_h2(v.z, v.w));
}

// ---------------- routing ----------------------------------------------------
__global__ void zero_kernel() {
    int t = threadIdx.x;
    if (t < NE) { g_counts[t] = 0; g_cursor[t] = 0; }
}

// router: rw cached in smem (stride 20 floats -> 16B-aligned rows, bank pattern
// {0,20,8,28,16,4,24,12} conflict-free for LDS.128), 16 tokens/block
__global__ __launch_bounds__(512) void router_kernel(
    const float* __restrict__ h, const float* __restrict__ rw)
{
    extern __shared__ float srw[];   // [DD][RT_STRIDE]
    int tid = threadIdx.x, lane = tid & 31, wid = tid >> 5;
    for (int i = tid; i < DD * NE; i += 512)
        srw[(i >> 4) * RT_STRIDE + (i & 15)] = rw[i];
    __syncthreads();

    int tok = blockIdx.x * RT_WARPS + wid;
    const float* x = h + (size_t)tok * DD;
    float acc[NE];
#pragma unroll
    for (int e = 0; e < NE; e++) acc[e] = 0.0f;
    for (int d = lane; d < DD; d += 32) {
        float xv = x[d];
        const float4* r4 = (const float4*)&srw[d * RT_STRIDE];
#pragma unroll
        for (int q = 0; q < 4; q++) {
            float4 rv = r4[q];
            acc[q * 4 + 0] += xv * rv.x;
            acc[q * 4 + 1] += xv * rv.y;
            acc[q * 4 + 2] += xv * rv.z;
            acc[q * 4 + 3] += xv * rv.w;
        }
    }
#pragma unroll
    for (int e = 0; e < NE; e++)
#pragma unroll
        for (int o = 16; o > 0; o >>= 1)
            acc[e] += __shfl_down_sync(0xFFFFFFFFu, acc[e], o);
    if (lane == 0) {
        int best = 0; float bv = acc[0];
#pragma unroll
        for (int e = 1; e < NE; e++)
            if (acc[e] > bv) { bv = acc[e]; best = e; }
        g_assign[tok] = best;
        g_wgt[tok]    = 1.0f / (1.0f + expf(-bv));
        atomicAdd(&g_counts[best], 1);
    }
}

__global__ void plan_kernel() {
    if (threadIdx.x != 0) return;
    int off = 0, t = 0;
    for (int e = 0; e < NE; e++) {
        g_row_start[e] = off;
        int c = g_counts[e];
        for (int r = 0; r < c; r += BM) {
            g_tile_e[t] = e; g_tile_row[t] = off + r;
            g_tile_rows[t] = min(BM, c - r); t++;
        }
        off += c;
    }
    g_num_tiles = t;
}

// merged scatter+gather: block per token; computes sorted position, writes perm
// and the fp16 token row.
__global__ __launch_bounds__(256) void scatter_gather_kernel(const float* __restrict__ h) {
    __shared__ int spos;
    int tok = blockIdx.x;
    if (threadIdx.x == 0) {
        int e = g_assign[tok];
        int p = g_row_start[e] + atomicAdd(&g_cursor[e], 1);
        g_perm[p] = tok;
        spos = p;
    }
    __syncthreads();
    int pos = spos;
    const float4* src = (const float4*)(h + (size_t)tok * DD);
    uint2* dh = (uint2*)(g_xh + (size_t)pos * DD);
    dh[threadIdx.x] = cvt4(src[threadIdx.x]);
}

// ---------------- fp16 mma.sync grouped GEMM ---------------------------------
// 4 warps (2x2), 64x32 warp tiles, BK=64 (16/32 K-iters). A fp16 via cp.async.
// B loaded RAW FP32 via LDG, converted fp16 in-flight; sts_B overlapped with
// the MMA phase (issued between ks=1 and ks=2, into the other buffer).
// FINAL=false: epilogue GELU(acc+b1) -> hidden fp16
// FINAL=true : epilogue (acc+b2)*wgt -> out[perm] (fp32)

template<int K, int NN>
__device__ __forceinline__ void issue_stage_A(
    uint32_t sbase, int i, int tid, int row0, int rows, const char* gA)
{
    uint32_t st = sbase + (i & 1) * STAGE_BYTES;
    int kc = i * BK;
    // A: 128 rows x 8 16B-chunks = 1024 chunks, 8 per thread
#pragma unroll
    for (int s = 0; s < 8; s++) {
        int j = tid + s * NTHREADS_G;
        int m = j >> 3, c = j & 7;
        int mc = m < rows ? m : 0;
        const char* g = gA + ((size_t)(row0 + mc) * K + kc) * 2 + c * 16;
        uint32_t d = st + OA_H + m * A_STRIDE + c * 16;
        cp16(d, g, m < rows ? 16u : 0u);
    }
    cp_commit();
}

// load B fp32 tile (BK x BN = 64x64) for stage i: 8 float4 per thread
template<int NN>
__device__ __forceinline__ void ldg_B(
    const float* gB, int i, int tid, int n0, float4* breg)
{
    int kc = i * BK;
#pragma unroll
    for (int s = 0; s < 8; s++) {
        int j = tid + s * NTHREADS_G;   // 0..1023
        int kr = j >> 4, c = j & 15;    // row 0..63, float4-col 0..15
        breg[s] = __ldg((const float4*)(gB + (size_t)(kc + kr) * NN + n0 + c * 4));
    }
}

// convert + store B fp16 plane for stage i
__device__ __forceinline__ void sts_B(
    uint32_t sbase, int i, int tid, const float4* breg)
{
    uint32_t st = sbase + (i & 1) * STAGE_BYTES;
#pragma unroll
    for (int s = 0; s < 8; s++) {
        int j = tid + s * NTHREADS_G;
        int kr = j >> 4, c = j & 15;
        uint2 hv = cvt4(breg[s]);
        sts64(st + OB_H + kr * B_STRIDE + c * 8, hv.x, hv.y);
    }
}

template<int K, int NN, bool FINAL>
__global__ __launch_bounds__(NTHREADS_G) void gemm_mma_kernel(
    const __half* __restrict__ Ain,
    const float* __restrict__ Wsrc,
    const float* __restrict__ bsrc, float* __restrict__ out)
{
    extern __shared__ char smem[];
    int t = blockIdx.x;
    if (t >= g_num_tiles) return;
    int e    = g_tile_e[t];
    int row0 = g_tile_row[t];
    int rows = g_tile_rows[t];
    int n0   = blockIdx.y * BN;

    const char* gA = (const char*)Ain;
    const float* gB = Wsrc + (size_t)e * K * NN;
    const float* bpn = bsrc + (size_t)e * NN + n0;

    uint32_t sbase = smem_u32(smem);
    int tid = threadIdx.x, lane = tid & 31, wid = tid >> 5;
    int warp_m = wid & 1;      // 2 warps in M -> 64 rows each
    int warp_n = wid >> 1;     // 2 warps in N -> 32 cols each

    const int niter = K / BK;

    float acc[4][4][4];
#pragma unroll
    for (int mt = 0; mt < 4; mt++)
#pragma unroll
        for (int nt = 0; nt < 4; nt++)
#pragma unroll
            for (int q = 0; q < 4; q++) acc[mt][nt][q] = 0.0f;

    int lr16 = lane & 15, lc8 = lane >> 4;

    float4 breg[8];
    // prologue: stage 0
    issue_stage_A<K, NN>(sbase, 0, tid, row0, rows, gA);
    ldg_B<NN>(gB, 0, tid, n0, breg);
    asm volatile("cp.async.wait_group 0;" ::: "memory");
    sts_B(sbase, 0, tid, breg);
    __syncthreads();

    for (int i = 0; i < niter; i++) {
        bool more = (i + 1 < niter);
        if (more) {
            issue_stage_A<K, NN>(sbase, i + 1, tid, row0, rows, gA);
            ldg_B<NN>(gB, i + 1, tid, n0, breg);
        }

        uint32_t st = sbase + (i & 1) * STAGE_BYTES;
#pragma unroll
        for (int ks = 0; ks < 4; ks++) {
            // overlap next-stage B convert+store with the MMA phase
            if (ks == 2 && more) sts_B(sbase, i + 1, tid, breg);

            uint32_t ah[4][4], bh[2][4];
#pragma unroll
            for (int mt = 0; mt < 4; mt++) {
                uint32_t arow = warp_m * 64 + mt * 16 + lr16;
                ldsm_x4(ah[mt], st + OA_H + arow * A_STRIDE + ks * 32 + lc8 * 16);
            }
#pragma unroll
            for (int np = 0; np < 2; np++) {
                uint32_t brow = ks * 16 + lr16;
                uint32_t bcol = warp_n * 32 + np * 16 + lc8 * 8;
                ldsm_x4_t(bh[np], st + OB_H + brow * B_STRIDE + bcol * 2);
            }
#pragma unroll
            for (int mt = 0; mt < 4; mt++)
#pragma unroll
                for (int nt = 0; nt < 4; nt++)
                    mma_f16(acc[mt][nt], ah[mt], &bh[nt >> 1][(nt & 1) * 2]);
        }

        if (more) {
            asm volatile("cp.async.wait_group 0;" ::: "memory");
            __syncthreads();
        }
    }

    // ---- epilogue ----
    int lr = lane >> 2, lc = (lane & 3) * 2;
    int   tokr[4][2];
    float wr[4][2];
#pragma unroll
    for (int mt = 0; mt < 4; mt++)
#pragma unroll
        for (int hh = 0; hh < 2; hh++) {
            int ml = warp_m * 64 + mt * 16 + lr + hh * 8;
            if (FINAL && ml < rows) {
                int tok = g_perm[row0 + ml];
                tokr[mt][hh] = tok;
                wr[mt][hh]   = g_wgt[tok];
            } else {
                tokr[mt][hh] = 0; wr[mt][hh] = 0.f;
            }
        }

#pragma unroll
    for (int nt = 0; nt < 4; nt++) {
        int ncl = warp_n * 32 + nt * 8 + lc;
        float b0 = __ldg(bpn + ncl), b1 = __ldg(bpn + ncl + 1);
#pragma unroll
        for (int mt = 0; mt < 4; mt++)
#pragma unroll
            for (int hh = 0; hh < 2; hh++) {
                int ml = warp_m * 64 + mt * 16 + lr + hh * 8;
                if (ml >= rows) continue;
                float v0 = acc[mt][nt][2 * hh]     + b0;
                float v1 = acc[mt][nt][2 * hh + 1] + b1;
                if (FINAL) {
                    float w = wr[mt][hh];
                    float2* o = (float2*)(out + (size_t)tokr[mt][hh] * NN + n0 + ncl);
                    *o = make_float2(v0 * w, v1 * w);
                } else {
                    float g0 = gelu_erf(v0), g1 = gelu_erf(v1);
                    size_t idx = (size_t)(row0 + ml) * NN + n0 + ncl;
                    *(uint32_t*)(g_hh + idx) = pack_h2(g0, g1);
                }
            }
    }
}

// ---------------- launch -----------------------------------------------------
extern "C" void kernel_launch(void* const* d_in, const int* in_sizes, int n_in,
                              void* d_out, int out_size)
{
    const float* h  = (const float*)d_in[0];   // (B,S,D)
    const float* rw = (const float*)d_in[1];   // (D,E)
    const float* w1 = (const float*)d_in[2];   // (E,D,F)
    const float* b1 = (const float*)d_in[3];   // (E,F)
    const float* w2 = (const float*)d_in[4];   // (E,F,D)
    const float* b2 = (const float*)d_in[5];   // (E,D)
    float* out = (float*)d_out;                // (B,S,D)

    cudaFuncSetAttribute(gemm_mma_kernel<DD, FF, false>,
                         cudaFuncAttributeMaxDynamicSharedMemorySize, SMEM_GEMM);
    cudaFuncSetAttribute(gemm_mma_kernel<FF, DD, true>,
                         cudaFuncAttributeMaxDynamicSharedMemorySize, SMEM_GEMM);
    cudaFuncSetAttribute(router_kernel,
                         cudaFuncAttributeMaxDynamicSharedMemorySize, SMEM_RT);

    __half *xh, *hh;
    cudaGetSymbolAddress((void**)&xh, g_xh);
    cudaGetSymbolAddress((void**)&hh, g_hh);

    zero_kernel<<<1, 32>>>();
    router_kernel<<<NTOK / RT_WARPS, 512, SMEM_RT>>>(h, rw);
    plan_kernel<<<1, 32>>>();
    scatter_gather_kernel<<<NTOK, 256>>>(h);

    gemm_mma_kernel<DD, FF, false><<<dim3(GRID_X, FF / BN), NTHREADS_G, SMEM_GEMM>>>(
        xh, w1, b1, nullptr);
    gemm_mma_kernel<FF, DD, true><<<dim3(GRID_X, DD / BN), NTHREADS_G, SMEM_GEMM>>>(
        hh, w2, b2, out);
}